// round 15
// baseline (speedup 1.0000x reference)
#include <cuda_runtime.h>
#include <math.h>

typedef unsigned long long U64;

#define FMA2(d, a, b) \
    asm("fma.rn.f32x2 %0, %1, %2, %3;" : "=l"(d) : "l"(a), "l"(b), "l"(d))
#define SPLAT2(d, s) \
    asm("mov.b64 %0, {%1, %1};" : "=l"(d) : "f"(s))

// Two-kernel split tensor-product conv:
//  K1 (a,z,p,pb): S_partial[33,228] = sum_{b half} h~[32p..] outer G -> scratch
//  K2 (a,z,po): stage S[65] (sum 4 partials, stride 226, 224 valid cols),
//               compute outputs [16po,16po+16) with 16-way H-split per output.
// G mem-column permutation (lane tx owns mem {4tx..4tx+3, 128+2tx, 129+2tx, 192+tx}):
//   L<128: mem = 4*(L%32)+L/32 ; 128<=L<192: mem = 128+2*((L-128)%32)+(L-128)/32
//   L>=192: mem = L
#define SROW 228
#define SROW2 226                       // mod 32 = 2 -> 16 consecutive rows, 16 banks
#define SPIECE (33 * SROW)              // 7524 floats per piece
__device__ float g_S[1280 * SPIECE];    // [p*2+pb][z][a][33][228]  (38.5 MB)

__global__ void __launch_bounds__(256, 3)
conv_s_kernel(const float* __restrict__ feat,
              const float* __restrict__ geo,
              const float* __restrict__ W1,
              const float* __restrict__ b1)
{
    constexpr int A = 160, DIM = 64;
    constexpr float C0   = 0.28209479177387814f;
    constexpr float NC00 = 0.6266570686577501f;
    constexpr float NC01 = 1.0854018854473597f;
    constexpr float NC10 = 0.4431134627263790f;
    constexpr float NC11 = 0.7674950356098778f;
    constexpr float NCZ0 = 0.8862269254527580f;
    constexpr float NCZ1 = 1.5349900712197556f;
    constexpr float E1   = 0.19947114020071635f;
    constexpr float AL   = 0.34549414947133547f;
    constexpr float C0S3 = 0.16286750396763996f;
    constexpr float QZ   = 0.05758236f;

    extern __shared__ float sm[];
    float* w1s = sm;             // [32] this piece's H-slice of W1
    float* b1s = sm + 64;        // [32]
    // staging buffer k at 128 + k*4160: G[16][224] (3584) then h[32][18] (576)

    const int a = blockIdx.x, z = blockIdx.y;
    const int p = blockIdx.z >> 1, pb = blockIdx.z & 1;
    const int tid = threadIdx.x;
    if (tid < 32) { w1s[tid] = W1[32 * p + tid]; b1s[tid] = b1[32 * p + tid]; }
    __syncthreads();

    const int ty = tid >> 5, tx = tid & 31;   // consumer: local rows ty+8m, slice tx
    const int bl = tid >> 4, vv = tid & 15;   // builder: 16 threads per b

    U64   S2[4][3];
    float S1[4];
    #pragma unroll
    for (int m = 0; m < 4; m++) {
        S2[m][0] = 0; S2[m][1] = 0; S2[m][2] = 0; S1[m] = 0.0f;
    }
    // bias row (global H=64): only p==1 pieces, warp ty==0
    const float h8 = (p == 1 && ty == 0) ? 1.0f : 0.0f;
    U64 hp8; SPLAT2(hp8, h8);
    U64 D2[3] = {0, 0, 0};
    float D1 = 0.0f;

    const float* geoA = geo + (size_t)((z * A + a) * A) * 3;
    const float* fz   = feat + (size_t)z * A * DIM;
    const int bbase = 80 * pb;

    // prefetch chunk 0
    float gx, gy, gz, f0v, p0, p1, p2;
    {
        const int b = bbase + bl;
        gx = __ldg(geoA + b * 3 + 0);
        gy = __ldg(geoA + b * 3 + 1);
        gz = __ldg(geoA + b * 3 + 2);
        const float* f = fz + b * DIM;
        f0v = __ldg(f + vv);
        p0 = __ldg(f + 16 + 3 * vv);
        p1 = __ldg(f + 17 + 3 * vv);
        p2 = __ldg(f + 18 + 3 * vv);
    }

    for (int c = 0; c < 5; c++) {
        float* gbuf = sm + 128 + (c & 1) * 4160;
        float* hbuf = gbuf + 3584;

        // ---- build G[14 groups] + h[2 local rows] from prefetched regs ----
        {
            const float r  = sqrtf(gx * gx + gy * gy + gz * gz);
            const bool is0 = (r == 0.0f);
            const float inv = is0 ? 1.0f : (1.0f / r);
            const float v0 = gy * inv, v1 = gz * inv, v2 = gx * inv;
            const float sdot = v0 * p0 + v1 * p1 + v2 * p2;
            const float ncA = is0 ? NCZ0 : NC00;
            const float ncB = is0 ? NCZ1 : NC01;
            const float ncC = is0 ? NCZ0 : NC10;
            const float ncD = is0 ? NCZ1 : NC11;

            float* G = gbuf + bl * 224;
            G[4 * vv]      = ncA * C0 * f0v;               // L = v
            G[64 + 4 * vv] = ncB * C0 * sdot;              // L = 16+v
            const float t2 = ncC * C0 * f0v;
            G[4 * vv + 1]  = t2 * v0;                      // L = 32+v
            G[65 + 4 * vv] = t2 * v1;                      // L = 48+v
            G[4 * vv + 2]  = t2 * v2;                      // L = 64+v
            const float t3a = ncD * C0S3;
            G[66 + 4 * vv] = t3a * p0;                     // L = 80+v
            G[4 * vv + 3]  = t3a * p1;                     // L = 96+v
            G[67 + 4 * vv] = t3a * p2;                     // L = 112+v
            const float t3b = ncD * E1;
            G[128 + 2 * vv] = t3b * (p1 * v2 - p2 * v1);   // L = 128+v
            G[160 + 2 * vv] = t3b * (p2 * v0 - p0 * v2);   // L = 144+v
            G[129 + 2 * vv] = t3b * (p0 * v1 - p1 * v0);   // L = 160+v
            if (!is0) {
                const float t3c = ncD * AL;
                G[161 + 2 * vv] = t3c * (v0 * sdot - p0 * (1.0f / 3.0f));
                G[192 + vv]     = t3c * (v1 * sdot - p1 * (1.0f / 3.0f));
                G[208 + vv]     = t3c * (v2 * sdot - p2 * (1.0f / 3.0f));
            } else {
                const float q = ncD * QZ;
                G[161 + 2 * vv] = q * p0;
                G[192 + vv]     = -2.0f * q * p1;
                G[208 + vv]     = q * p2;
            }
            // h transposed: h[lh][18], lh = vv + 16m (local), column = bl
            #pragma unroll
            for (int m = 0; m < 2; m++) {
                const int lh = vv + 16 * m;
                hbuf[lh * 18 + bl] = fmaxf(fmaf(r, w1s[lh], b1s[lh]), 0.0f);
            }
        }

        // ---- prefetch next chunk (hidden under sync + FMA loop) ----
        if (c < 4) {
            const int b = bbase + (c + 1) * 16 + bl;
            gx = __ldg(geoA + b * 3 + 0);
            gy = __ldg(geoA + b * 3 + 1);
            gz = __ldg(geoA + b * 3 + 2);
            const float* f = fz + b * DIM;
            f0v = __ldg(f + vv);
            p0 = __ldg(f + 16 + 3 * vv);
            p1 = __ldg(f + 17 + 3 * vv);
            p2 = __ldg(f + 18 + 3 * vv);
        }
        __syncthreads();   // single sync per chunk (double buffered)

        // ---- rank-16 update, 2 j's per iteration ----
        #pragma unroll 2
        for (int g16 = 0; g16 < 8; g16++) {
            float2 h2[4];
            #pragma unroll
            for (int m = 0; m < 4; m++)
                h2[m] = *(const float2*)(hbuf + (ty + 8 * m) * 18 + 2 * g16);
            #pragma unroll
            for (int jj = 0; jj < 2; jj++) {
                const float* grow = gbuf + (2 * g16 + jj) * 224;
                const ulonglong2 gg = *(const ulonglong2*)(grow + 4 * tx);
                const U64 g45 = *(const U64*)(grow + 128 + 2 * tx);
                const float gc = grow[192 + tx];
                #pragma unroll
                for (int m = 0; m < 4; m++) {
                    const float hs = jj ? h2[m].y : h2[m].x;
                    U64 hp; SPLAT2(hp, hs);
                    FMA2(S2[m][0], hp, gg.x);
                    FMA2(S2[m][1], hp, gg.y);
                    FMA2(S2[m][2], hp, g45);
                    S1[m] = fmaf(hs, gc, S1[m]);
                }
                FMA2(D2[0], hp8, gg.x);     // bias row (p==1, ty==0 only nonzero)
                FMA2(D2[1], hp8, gg.y);
                FMA2(D2[2], hp8, g45);
                D1 = fmaf(h8, gc, D1);
            }
        }
    }

    // ---- spill S partial straight to global scratch (coalesced) ----
    float* base = g_S + (size_t)((blockIdx.z * 2 + z) * A + a) * SPIECE;
    #pragma unroll
    for (int m = 0; m < 4; m++) {
        float* rp = base + (ty + 8 * m) * SROW;
        const float2 s01 = *(const float2*)&S2[m][0];
        const float2 s23 = *(const float2*)&S2[m][1];
        *(float4*)(rp + 4 * tx) = make_float4(s01.x, s01.y, s23.x, s23.y);
        *(float2*)(rp + 128 + 2 * tx) = *(const float2*)&S2[m][2];
        rp[192 + tx] = S1[m];
    }
    if (p == 1 && ty == 0) {   // bias row -> local row 32
        float* rp = base + 32 * SROW;
        const float2 d01 = *(const float2*)&D2[0];
        const float2 d23 = *(const float2*)&D2[1];
        *(float4*)(rp + 4 * tx) = make_float4(d01.x, d01.y, d23.x, d23.y);
        *(float2*)(rp + 128 + 2 * tx) = *(const float2*)&D2[2];
        rp[192 + tx] = D1;
    }
}

// ---- kernel 2: stage summed S, contract outputs [16po,16po+16) ----
__global__ void __launch_bounds__(256, 3)
out_kernel(const float* __restrict__ W2,
           const float* __restrict__ b2p,
           const float* __restrict__ maskp,
           float* __restrict__ out)
{
    constexpr int A = 160, DIM = 64;
    extern __shared__ float S_sh[];     // [65][226], 224 valid cols

    const int a = blockIdx.x, z = blockIdx.y, po = blockIdx.z;
    const int tid = threadIdx.x;

    const float* P00 = g_S + (size_t)((0 * 2 + z) * A + a) * SPIECE;  // p0 pb0
    const float* P01 = g_S + (size_t)((1 * 2 + z) * A + a) * SPIECE;  // p0 pb1
    const float* P10 = g_S + (size_t)((2 * 2 + z) * A + a) * SPIECE;  // p1 pb0
    const float* P11 = g_S + (size_t)((3 * 2 + z) * A + a) * SPIECE;  // p1 pb1

    // stage 65 rows x 56 float4 (exactly the 224 valid cols; stride 226)
    for (int i = tid; i < 65 * 56; i += 256) {
        const int row = i / 56, c4 = i % 56;
        const float *q0, *q1;
        int lrow;
        if (row < 32)      { q0 = P00; q1 = P01; lrow = row; }
        else if (row < 64) { q0 = P10; q1 = P11; lrow = row - 32; }
        else               { q0 = P10; q1 = P11; lrow = 32; }     // bias row
        const float4 x0 = *(const float4*)(q0 + lrow * SROW + 4 * c4);
        const float4 x1 = *(const float4*)(q1 + lrow * SROW + 4 * c4);
        float* d = S_sh + row * SROW2 + 4 * c4;
        ((float2*)d)[0] = make_float2(x0.x + x1.x, x0.y + x1.y);
        ((float2*)d)[1] = make_float2(x0.z + x1.z, x0.w + x1.w);
    }
    __syncthreads();

    // 16 outputs per CTA, 16 H-parts per output: rows lh = 16t + part
    const int ol = tid >> 4, part = tid & 15;
    const int oi = po * 16 + ol;
    float acc = 0.0f;
    const int tcnt = (part == 0) ? 5 : 4;
    if (po == 0) {                                   // l=0 outputs (u = oi)
        const int u = oi;
        for (int t = 0; t < tcnt; t++) {
            const int hh = (t == 4) ? 64 : (16 * t + part);
            const float4* w4 = (const float4*)((hh == 64) ? b2p
                                   : (W2 + (size_t)hh * 1536));
            const float* Sr = S_sh + hh * SROW2;
            #pragma unroll
            for (int v4 = 0; v4 < 4; v4++) {
                const float4 wa = w4[u * 4 + v4];        // W2[hh, u*16+v]
                const float4 wb = w4[64 + u * 4 + v4];   // W2[hh, 256+u*16+v]
                const int mb = 16 * v4;                  // mem col 4v
                acc = fmaf(wa.x, Sr[mb + 0],  acc);
                acc = fmaf(wa.y, Sr[mb + 4],  acc);
                acc = fmaf(wa.z, Sr[mb + 8],  acc);
                acc = fmaf(wa.w, Sr[mb + 12], acc);
                acc = fmaf(wb.x, Sr[64 + mb + 0],  acc);
                acc = fmaf(wb.y, Sr[64 + mb + 4],  acc);
                acc = fmaf(wb.z, Sr[64 + mb + 8],  acc);
                acc = fmaf(wb.w, Sr[64 + mb + 12], acc);
            }
        }
    } else {                                         // l=1 outputs (u, i)
        const int qq = oi - 16;
        const int u  = qq / 3;
        const int i  = qq - 3 * u;
        const int B2  = (i == 0) ? 1   : (i == 1) ? 65  : 2;    // lf=1 (l_in=0)
        const int B3A = (i == 0) ? 66  : (i == 1) ? 3   : 67;   // lf=0
        const int B3B = (i == 0) ? 128 : (i == 1) ? 160 : 129;  // lf=1
        const int B3C = (i == 0) ? 161 : (i == 1) ? 192 : 208;  // lf=2
        const int S3C = (i == 0) ? 2 : 1;
        for (int t = 0; t < tcnt; t++) {
            const int hh = (t == 4) ? 64 : (16 * t + part);
            const float4* w4 = (const float4*)((hh == 64) ? b2p
                                   : (W2 + (size_t)hh * 1536));
            const float* Sr = S_sh + hh * SROW2;
            #pragma unroll
            for (int v4 = 0; v4 < 4; v4++) {
                const float4 wcv = w4[128 + u * 4 + v4];         // W2[hh, 512+u*16+v]
                const float4 w0  = w4[192 + 12 * u + 3 * v4];    // W2[hh, 768+(u*16+v)*3+k]
                const float4 w1v = w4[193 + 12 * u + 3 * v4];
                const float4 w2v = w4[194 + 12 * u + 3 * v4];
                const int v = 4 * v4;
                #define L1V(vn, K0, K1, K2, WC)                       \
                    acc = fmaf(WC, Sr[B2  + 4 * (vn)], acc);          \
                    acc = fmaf(K0, Sr[B3A + 4 * (vn)], acc);          \
                    acc = fmaf(K1, Sr[B3B + 2 * (vn)], acc);          \
                    acc = fmaf(K2, Sr[B3C + S3C * (vn)], acc);
                L1V(v + 0, w0.x,  w0.y,  w0.z,  wcv.x)
                L1V(v + 1, w0.w,  w1v.x, w1v.y, wcv.y)
                L1V(v + 2, w1v.z, w1v.w, w2v.x, wcv.z)
                L1V(v + 3, w2v.y, w2v.z, w2v.w, wcv.w)
                #undef L1V
            }
        }
    }
    // reduce 16 H-parts (width-16 shfl segments)
    acc += __shfl_down_sync(0xffffffffu, acc, 8, 16);
    acc += __shfl_down_sync(0xffffffffu, acc, 4, 16);
    acc += __shfl_down_sync(0xffffffffu, acc, 2, 16);
    acc += __shfl_down_sync(0xffffffffu, acc, 1, 16);
    if (part == 0) {
        const float mv = maskp[z * A + a];
        out[(size_t)((z * A + a) * DIM) + oi] = acc * mv;
    }
}

extern "C" void kernel_launch(void* const* d_in, const int* in_sizes, int n_in,
                              void* d_out, int out_size)
{
    const float* feat  = (const float*)d_in[0];
    const float* geo   = (const float*)d_in[1];
    const float* maskp = (const float*)d_in[2];
    const float* W1    = (const float*)d_in[3];
    const float* b1    = (const float*)d_in[4];
    const float* W2    = (const float*)d_in[5];
    const float* b2    = (const float*)d_in[6];
    float* out = (float*)d_out;

    const int smem1 = 8448 * 4;             // 33,792 B (header + 2 staging buffers)
    const int smem2 = 65 * SROW2 * 4;       // 58,760 B
    cudaFuncSetAttribute(conv_s_kernel, cudaFuncAttributeMaxDynamicSharedMemorySize,
                         smem1);
    cudaFuncSetAttribute(out_kernel, cudaFuncAttributeMaxDynamicSharedMemorySize,
                         smem2);
    dim3 grid1(160, 2, 4);
    conv_s_kernel<<<grid1, 256, smem1>>>(feat, geo, W1, b1);
    dim3 grid2(160, 2, 4);
    out_kernel<<<grid2, 256, smem2>>>(W2, b2, maskp, out);
}

// round 16
// speedup vs baseline: 1.2716x; 1.2716x over previous
#include <cuda_runtime.h>
#include <math.h>

typedef unsigned long long U64;

#define FMA2(d, a, b) \
    asm("fma.rn.f32x2 %0, %1, %2, %3;" : "=l"(d) : "l"(a), "l"(b), "l"(d))
#define SPLAT2(d, s) \
    asm("mov.b64 %0, {%1, %1};" : "=l"(d) : "f"(s))

// Three-stage split tensor-product conv:
//  K1 (a,z,p,pb): S_partial[33,228] = sum_{b half pb} h~[32p..] outer G -> g_S
//  K2 (a,z,p):    stage S_p[33,228] = pb0+pb1 from L2; contract this H-slice
//                 with W2[32p..] (R11's conflict-free 4t+part layout) -> g_out
//  K3:            out = (g_out[p0] + g_out[p1]) * mask
// G mem-column permutation (lane tx owns mem {4tx..4tx+3, 128+2tx, 129+2tx, 192+tx}):
//   L<128: mem = 4*(L%32)+L/32 ; 128<=L<192: mem = 128+2*((L-128)%32)+(L-128)/32
//   L>=192: mem = L
#define SROW 228
#define SPIECE (33 * SROW)              // 7524 floats per piece
__device__ float g_S[1280 * SPIECE];    // [p*2+pb][z][a][33][228]  (38.5 MB)
__device__ float g_out[2 * 2 * 160 * 64];   // [p][z][a][64]

__global__ void __launch_bounds__(256, 3)
conv_s_kernel(const float* __restrict__ feat,
              const float* __restrict__ geo,
              const float* __restrict__ W1,
              const float* __restrict__ b1)
{
    constexpr int A = 160, DIM = 64;
    constexpr float C0   = 0.28209479177387814f;
    constexpr float NC00 = 0.6266570686577501f;
    constexpr float NC01 = 1.0854018854473597f;
    constexpr float NC10 = 0.4431134627263790f;
    constexpr float NC11 = 0.7674950356098778f;
    constexpr float NCZ0 = 0.8862269254527580f;
    constexpr float NCZ1 = 1.5349900712197556f;
    constexpr float E1   = 0.19947114020071635f;
    constexpr float AL   = 0.34549414947133547f;
    constexpr float C0S3 = 0.16286750396763996f;
    constexpr float QZ   = 0.05758236f;

    extern __shared__ float sm[];
    float* w1s = sm;             // [32] this piece's H-slice of W1
    float* b1s = sm + 64;        // [32]
    // staging buffer k at 128 + k*4160: G[16][224] (3584) then h[32][18] (576)

    const int a = blockIdx.x, z = blockIdx.y;
    const int p = blockIdx.z >> 1, pb = blockIdx.z & 1;
    const int tid = threadIdx.x;
    if (tid < 32) { w1s[tid] = W1[32 * p + tid]; b1s[tid] = b1[32 * p + tid]; }
    __syncthreads();

    const int ty = tid >> 5, tx = tid & 31;   // consumer: local rows ty+8m, slice tx
    const int bl = tid >> 4, vv = tid & 15;   // builder: 16 threads per b

    U64   S2[4][3];
    float S1[4];
    #pragma unroll
    for (int m = 0; m < 4; m++) {
        S2[m][0] = 0; S2[m][1] = 0; S2[m][2] = 0; S1[m] = 0.0f;
    }
    // bias row (global H=64): only p==1 pieces, warp ty==0
    const float h8 = (p == 1 && ty == 0) ? 1.0f : 0.0f;
    U64 hp8; SPLAT2(hp8, h8);
    U64 D2[3] = {0, 0, 0};
    float D1 = 0.0f;

    const float* geoA = geo + (size_t)((z * A + a) * A) * 3;
    const float* fz   = feat + (size_t)z * A * DIM;
    const int bbase = 80 * pb;

    // prefetch chunk 0
    float gx, gy, gz, f0v, p0, p1, p2;
    {
        const int b = bbase + bl;
        gx = __ldg(geoA + b * 3 + 0);
        gy = __ldg(geoA + b * 3 + 1);
        gz = __ldg(geoA + b * 3 + 2);
        const float* f = fz + b * DIM;
        f0v = __ldg(f + vv);
        p0 = __ldg(f + 16 + 3 * vv);
        p1 = __ldg(f + 17 + 3 * vv);
        p2 = __ldg(f + 18 + 3 * vv);
    }

    for (int c = 0; c < 5; c++) {
        float* gbuf = sm + 128 + (c & 1) * 4160;
        float* hbuf = gbuf + 3584;

        // ---- build G[14 groups] + h[2 local rows] from prefetched regs ----
        {
            const float r  = sqrtf(gx * gx + gy * gy + gz * gz);
            const bool is0 = (r == 0.0f);
            const float inv = is0 ? 1.0f : (1.0f / r);
            const float v0 = gy * inv, v1 = gz * inv, v2 = gx * inv;
            const float sdot = v0 * p0 + v1 * p1 + v2 * p2;
            const float ncA = is0 ? NCZ0 : NC00;
            const float ncB = is0 ? NCZ1 : NC01;
            const float ncC = is0 ? NCZ0 : NC10;
            const float ncD = is0 ? NCZ1 : NC11;

            float* G = gbuf + bl * 224;
            G[4 * vv]      = ncA * C0 * f0v;               // L = v
            G[64 + 4 * vv] = ncB * C0 * sdot;              // L = 16+v
            const float t2 = ncC * C0 * f0v;
            G[4 * vv + 1]  = t2 * v0;                      // L = 32+v
            G[65 + 4 * vv] = t2 * v1;                      // L = 48+v
            G[4 * vv + 2]  = t2 * v2;                      // L = 64+v
            const float t3a = ncD * C0S3;
            G[66 + 4 * vv] = t3a * p0;                     // L = 80+v
            G[4 * vv + 3]  = t3a * p1;                     // L = 96+v
            G[67 + 4 * vv] = t3a * p2;                     // L = 112+v
            const float t3b = ncD * E1;
            G[128 + 2 * vv] = t3b * (p1 * v2 - p2 * v1);   // L = 128+v
            G[160 + 2 * vv] = t3b * (p2 * v0 - p0 * v2);   // L = 144+v
            G[129 + 2 * vv] = t3b * (p0 * v1 - p1 * v0);   // L = 160+v
            if (!is0) {
                const float t3c = ncD * AL;
                G[161 + 2 * vv] = t3c * (v0 * sdot - p0 * (1.0f / 3.0f));
                G[192 + vv]     = t3c * (v1 * sdot - p1 * (1.0f / 3.0f));
                G[208 + vv]     = t3c * (v2 * sdot - p2 * (1.0f / 3.0f));
            } else {
                const float q = ncD * QZ;
                G[161 + 2 * vv] = q * p0;
                G[192 + vv]     = -2.0f * q * p1;
                G[208 + vv]     = q * p2;
            }
            // h transposed: h[lh][18], lh = vv + 16m (local), column = bl
            #pragma unroll
            for (int m = 0; m < 2; m++) {
                const int lh = vv + 16 * m;
                hbuf[lh * 18 + bl] = fmaxf(fmaf(r, w1s[lh], b1s[lh]), 0.0f);
            }
        }

        // ---- prefetch next chunk (hidden under sync + FMA loop) ----
        if (c < 4) {
            const int b = bbase + (c + 1) * 16 + bl;
            gx = __ldg(geoA + b * 3 + 0);
            gy = __ldg(geoA + b * 3 + 1);
            gz = __ldg(geoA + b * 3 + 2);
            const float* f = fz + b * DIM;
            f0v = __ldg(f + vv);
            p0 = __ldg(f + 16 + 3 * vv);
            p1 = __ldg(f + 17 + 3 * vv);
            p2 = __ldg(f + 18 + 3 * vv);
        }
        __syncthreads();   // single sync per chunk (double buffered)

        // ---- rank-16 update, 2 j's per iteration ----
        #pragma unroll 2
        for (int g16 = 0; g16 < 8; g16++) {
            float2 h2[4];
            #pragma unroll
            for (int m = 0; m < 4; m++)
                h2[m] = *(const float2*)(hbuf + (ty + 8 * m) * 18 + 2 * g16);
            #pragma unroll
            for (int jj = 0; jj < 2; jj++) {
                const float* grow = gbuf + (2 * g16 + jj) * 224;
                const ulonglong2 gg = *(const ulonglong2*)(grow + 4 * tx);
                const U64 g45 = *(const U64*)(grow + 128 + 2 * tx);
                const float gc = grow[192 + tx];
                #pragma unroll
                for (int m = 0; m < 4; m++) {
                    const float hs = jj ? h2[m].y : h2[m].x;
                    U64 hp; SPLAT2(hp, hs);
                    FMA2(S2[m][0], hp, gg.x);
                    FMA2(S2[m][1], hp, gg.y);
                    FMA2(S2[m][2], hp, g45);
                    S1[m] = fmaf(hs, gc, S1[m]);
                }
                FMA2(D2[0], hp8, gg.x);     // bias row (p==1, ty==0 only nonzero)
                FMA2(D2[1], hp8, gg.y);
                FMA2(D2[2], hp8, g45);
                D1 = fmaf(h8, gc, D1);
            }
        }
    }

    // ---- spill S partial straight to global scratch (coalesced) ----
    float* base = g_S + (size_t)((blockIdx.z * 2 + z) * A + a) * SPIECE;
    #pragma unroll
    for (int m = 0; m < 4; m++) {
        float* rp = base + (ty + 8 * m) * SROW;
        const float2 s01 = *(const float2*)&S2[m][0];
        const float2 s23 = *(const float2*)&S2[m][1];
        *(float4*)(rp + 4 * tx) = make_float4(s01.x, s01.y, s23.x, s23.y);
        *(float2*)(rp + 128 + 2 * tx) = *(const float2*)&S2[m][2];
        rp[192 + tx] = S1[m];
    }
    if (p == 1 && ty == 0) {   // bias row -> local row 32
        float* rp = base + 32 * SROW;
        const float2 d01 = *(const float2*)&D2[0];
        const float2 d23 = *(const float2*)&D2[1];
        *(float4*)(rp + 4 * tx) = make_float4(d01.x, d01.y, d23.x, d23.y);
        *(float2*)(rp + 128 + 2 * tx) = *(const float2*)&D2[2];
        rp[192 + tx] = D1;
    }
}

// ---- kernel 2: per H-slice, sum pb pieces and contract (R11 phase-2) ----
__global__ void __launch_bounds__(256, 3)
out_kernel(const float* __restrict__ W2,
           const float* __restrict__ b2p)
{
    constexpr int A = 160, DIM = 64;
    extern __shared__ float S_sh[];     // [33][228]

    const int a = blockIdx.x, z = blockIdx.y, p = blockIdx.z;
    const int tid = threadIdx.x;

    const float* Q0 = g_S + (size_t)(((p * 2 + 0) * 2 + z) * A + a) * SPIECE;
    const float* Q1 = g_S + (size_t)(((p * 2 + 1) * 2 + z) * A + a) * SPIECE;

    // stage 33 rows x 56 float4 (224 valid cols), stride 228 (16B aligned rows)
    for (int i = tid; i < 33 * 56; i += 256) {
        const int row = i / 56, c4 = i % 56;
        const float4 x0 = *(const float4*)(Q0 + row * SROW + 4 * c4);
        const float4 x1 = *(const float4*)(Q1 + row * SROW + 4 * c4);
        *(float4*)(S_sh + row * SROW + 4 * c4) =
            make_float4(x0.x + x1.x, x0.y + x1.y, x0.z + x1.z, x0.w + x1.w);
    }
    __syncthreads();

    // phase 2 (R11-proven): part -> consecutive rows lh = 4t+part
    const int oi = tid >> 2, part = tid & 3;
    float acc = 0.0f;
    const int hcnt = (part == 0 && p == 1) ? 9 : 8;
    if (oi < 16) {                                   // l=0 outputs (u = oi)
        const int u = oi;
        for (int t = 0; t < hcnt; t++) {
            const int lh = (t == 8) ? 32 : (4 * t + part);
            const float4* w4 = (const float4*)((lh == 32) ? b2p
                                   : (W2 + (size_t)(32 * p + lh) * 1536));
            const float* Sr = S_sh + lh * SROW;
            #pragma unroll
            for (int v4 = 0; v4 < 4; v4++) {
                const float4 wa = w4[u * 4 + v4];        // W2[hh, u*16+v]
                const float4 wb = w4[64 + u * 4 + v4];   // W2[hh, 256+u*16+v]
                const int mb = 16 * v4;                  // mem col 4v
                acc = fmaf(wa.x, Sr[mb + 0],  acc);
                acc = fmaf(wa.y, Sr[mb + 4],  acc);
                acc = fmaf(wa.z, Sr[mb + 8],  acc);
                acc = fmaf(wa.w, Sr[mb + 12], acc);
                acc = fmaf(wb.x, Sr[64 + mb + 0],  acc);
                acc = fmaf(wb.y, Sr[64 + mb + 4],  acc);
                acc = fmaf(wb.z, Sr[64 + mb + 8],  acc);
                acc = fmaf(wb.w, Sr[64 + mb + 12], acc);
            }
        }
    } else {                                         // l=1 outputs (u, i)
        const int qq = oi - 16;
        const int u  = qq / 3;
        const int i  = qq - 3 * u;
        const int B2  = (i == 0) ? 1   : (i == 1) ? 65  : 2;    // lf=1 (l_in=0)
        const int B3A = (i == 0) ? 66  : (i == 1) ? 3   : 67;   // lf=0
        const int B3B = (i == 0) ? 128 : (i == 1) ? 160 : 129;  // lf=1
        const int B3C = (i == 0) ? 161 : (i == 1) ? 192 : 208;  // lf=2
        const int S3C = (i == 0) ? 2 : 1;
        for (int t = 0; t < hcnt; t++) {
            const int lh = (t == 8) ? 32 : (4 * t + part);
            const float4* w4 = (const float4*)((lh == 32) ? b2p
                                   : (W2 + (size_t)(32 * p + lh) * 1536));
            const float* Sr = S_sh + lh * SROW;
            #pragma unroll
            for (int v4 = 0; v4 < 4; v4++) {
                const float4 wcv = w4[128 + u * 4 + v4];         // W2[hh, 512+u*16+v]
                const float4 w0  = w4[192 + 12 * u + 3 * v4];    // W2[hh, 768+(u*16+v)*3+k]
                const float4 w1v = w4[193 + 12 * u + 3 * v4];
                const float4 w2v = w4[194 + 12 * u + 3 * v4];
                const int v = 4 * v4;
                #define L1V(vn, K0, K1, K2, WC)                       \
                    acc = fmaf(WC, Sr[B2  + 4 * (vn)], acc);          \
                    acc = fmaf(K0, Sr[B3A + 4 * (vn)], acc);          \
                    acc = fmaf(K1, Sr[B3B + 2 * (vn)], acc);          \
                    acc = fmaf(K2, Sr[B3C + S3C * (vn)], acc);
                L1V(v + 0, w0.x,  w0.y,  w0.z,  wcv.x)
                L1V(v + 1, w0.w,  w1v.x, w1v.y, wcv.y)
                L1V(v + 2, w1v.z, w1v.w, w2v.x, wcv.z)
                L1V(v + 3, w2v.y, w2v.z, w2v.w, wcv.w)
                #undef L1V
            }
        }
    }
    acc += __shfl_down_sync(0xffffffffu, acc, 1);
    acc += __shfl_down_sync(0xffffffffu, acc, 2);
    if (part == 0)
        g_out[(size_t)(((p * 2 + z) * A + a) * DIM) + oi] = acc;
}

__global__ void reduce_kernel(const float* __restrict__ maskp,
                              float* __restrict__ out)
{
    constexpr int NN = 2 * 160 * 64;
    const int i = blockIdx.x * 256 + threadIdx.x;
    if (i < NN) {
        const float s = g_out[i] + g_out[NN + i];
        out[i] = s * __ldg(maskp + (i >> 6));
    }
}

extern "C" void kernel_launch(void* const* d_in, const int* in_sizes, int n_in,
                              void* d_out, int out_size)
{
    const float* feat  = (const float*)d_in[0];
    const float* geo   = (const float*)d_in[1];
    const float* maskp = (const float*)d_in[2];
    const float* W1    = (const float*)d_in[3];
    const float* b1    = (const float*)d_in[4];
    const float* W2    = (const float*)d_in[5];
    const float* b2    = (const float*)d_in[6];
    float* out = (float*)d_out;

    const int smem1 = 8448 * 4;             // 33,792 B (header + 2 staging buffers)
    const int smem2 = 33 * SROW * 4;        // 30,096 B
    cudaFuncSetAttribute(conv_s_kernel, cudaFuncAttributeMaxDynamicSharedMemorySize,
                         smem1);
    cudaFuncSetAttribute(out_kernel, cudaFuncAttributeMaxDynamicSharedMemorySize,
                         smem2);
    dim3 grid1(160, 2, 4);
    conv_s_kernel<<<grid1, 256, smem1>>>(feat, geo, W1, b1);
    dim3 grid2(160, 2, 2);
    out_kernel<<<grid2, 256, smem2>>>(W2, b2);
    reduce_kernel<<<(2 * 160 * 64 + 255) / 256, 256>>>(maskp, out);
}

// round 17
// speedup vs baseline: 1.4435x; 1.1352x over previous
#include <cuda_runtime.h>
#include <math.h>

typedef unsigned long long U64;

#define FMA2(d, a, b) \
    asm("fma.rn.f32x2 %0, %1, %2, %3;" : "=l"(d) : "l"(a), "l"(b), "l"(d))
#define SPLAT2(d, s) \
    asm("mov.b64 %0, {%1, %1};" : "=l"(d) : "f"(s))

// Four-stage split tensor-product conv:
//  P0 prep: g_Wk[row][u][k][16v] = W2row[768+3*(u*16+v)+k]  (v-contiguous repack)
//  K1 (a,z,p,pb): S_partial[33,228] = sum_{b half pb} h~[32p..] outer G -> g_S
//                 (G columns PERMUTED; see map below)
//  K2 (a,p): stage S for BOTH z in LOGICAL col order (un-permute), contract
//            H-slice with W2/Wk via fma.f32x2 -> g_out[p][z]
//  K3: out = (g_out[p0] + g_out[p1]) * mask
// G mem-column permutation (lane tx owns mem {4tx..4tx+3, 128+2tx, 129+2tx, 192+tx}):
//   L<128: mem = 4*(L%32)+L/32 ; 128<=L<192: mem = 128+2*((L-128)%32)+(L-128)/32
//   L>=192: mem = L
#define SROW 228
#define SPIECE (33 * SROW)              // 7524 floats per piece
__device__ float g_S[1280 * SPIECE];    // [p*2+pb][z][a][33][228]  (38.5 MB)
__device__ float g_out[2 * 2 * 160 * 64];   // [p][z][a][64]
__device__ float g_Wk[65 * 16 * 3 * 16];    // [row][u][k][v]  (200 KB)

__global__ void prep_w_kernel(const float* __restrict__ W2,
                              const float* __restrict__ b2p)
{
    const int row = blockIdx.x;                       // 0..64 (64 = bias)
    const float* Wr = (row == 64) ? b2p : (W2 + (size_t)row * 1536);
    for (int idx = threadIdx.x; idx < 768; idx += 256) {
        const int u = idx / 48, rem = idx % 48;
        const int k = rem / 16, v = rem % 16;
        g_Wk[row * 768 + idx] = Wr[768 + 3 * (u * 16 + v) + k];
    }
}

__global__ void __launch_bounds__(256, 3)
conv_s_kernel(const float* __restrict__ feat,
              const float* __restrict__ geo,
              const float* __restrict__ W1,
              const float* __restrict__ b1)
{
    constexpr int A = 160, DIM = 64;
    constexpr float C0   = 0.28209479177387814f;
    constexpr float NC00 = 0.6266570686577501f;
    constexpr float NC01 = 1.0854018854473597f;
    constexpr float NC10 = 0.4431134627263790f;
    constexpr float NC11 = 0.7674950356098778f;
    constexpr float NCZ0 = 0.8862269254527580f;
    constexpr float NCZ1 = 1.5349900712197556f;
    constexpr float E1   = 0.19947114020071635f;
    constexpr float AL   = 0.34549414947133547f;
    constexpr float C0S3 = 0.16286750396763996f;
    constexpr float QZ   = 0.05758236f;

    extern __shared__ float sm[];
    float* w1s = sm;             // [32] this piece's H-slice of W1
    float* b1s = sm + 64;        // [32]
    // staging buffer k at 128 + k*4160: G[16][224] (3584) then h[32][18] (576)

    const int a = blockIdx.x, z = blockIdx.y;
    const int p = blockIdx.z >> 1, pb = blockIdx.z & 1;
    const int tid = threadIdx.x;
    if (tid < 32) { w1s[tid] = W1[32 * p + tid]; b1s[tid] = b1[32 * p + tid]; }
    __syncthreads();

    const int ty = tid >> 5, tx = tid & 31;   // consumer: local rows ty+8m, slice tx
    const int bl = tid >> 4, vv = tid & 15;   // builder: 16 threads per b

    U64   S2[4][3];
    float S1[4];
    #pragma unroll
    for (int m = 0; m < 4; m++) {
        S2[m][0] = 0; S2[m][1] = 0; S2[m][2] = 0; S1[m] = 0.0f;
    }
    const float h8 = (p == 1 && ty == 0) ? 1.0f : 0.0f;
    U64 hp8; SPLAT2(hp8, h8);
    U64 D2[3] = {0, 0, 0};
    float D1 = 0.0f;

    const float* geoA = geo + (size_t)((z * A + a) * A) * 3;
    const float* fz   = feat + (size_t)z * A * DIM;
    const int bbase = 80 * pb;

    float gx, gy, gz, f0v, p0, p1, p2;
    {
        const int b = bbase + bl;
        gx = __ldg(geoA + b * 3 + 0);
        gy = __ldg(geoA + b * 3 + 1);
        gz = __ldg(geoA + b * 3 + 2);
        const float* f = fz + b * DIM;
        f0v = __ldg(f + vv);
        p0 = __ldg(f + 16 + 3 * vv);
        p1 = __ldg(f + 17 + 3 * vv);
        p2 = __ldg(f + 18 + 3 * vv);
    }

    for (int c = 0; c < 5; c++) {
        float* gbuf = sm + 128 + (c & 1) * 4160;
        float* hbuf = gbuf + 3584;

        {
            const float r  = sqrtf(gx * gx + gy * gy + gz * gz);
            const bool is0 = (r == 0.0f);
            const float inv = is0 ? 1.0f : (1.0f / r);
            const float v0 = gy * inv, v1 = gz * inv, v2 = gx * inv;
            const float sdot = v0 * p0 + v1 * p1 + v2 * p2;
            const float ncA = is0 ? NCZ0 : NC00;
            const float ncB = is0 ? NCZ1 : NC01;
            const float ncC = is0 ? NCZ0 : NC10;
            const float ncD = is0 ? NCZ1 : NC11;

            float* G = gbuf + bl * 224;
            G[4 * vv]      = ncA * C0 * f0v;               // L = v
            G[64 + 4 * vv] = ncB * C0 * sdot;              // L = 16+v
            const float t2 = ncC * C0 * f0v;
            G[4 * vv + 1]  = t2 * v0;                      // L = 32+v
            G[65 + 4 * vv] = t2 * v1;                      // L = 48+v
            G[4 * vv + 2]  = t2 * v2;                      // L = 64+v
            const float t3a = ncD * C0S3;
            G[66 + 4 * vv] = t3a * p0;                     // L = 80+v
            G[4 * vv + 3]  = t3a * p1;                     // L = 96+v
            G[67 + 4 * vv] = t3a * p2;                     // L = 112+v
            const float t3b = ncD * E1;
            G[128 + 2 * vv] = t3b * (p1 * v2 - p2 * v1);   // L = 128+v
            G[160 + 2 * vv] = t3b * (p2 * v0 - p0 * v2);   // L = 144+v
            G[129 + 2 * vv] = t3b * (p0 * v1 - p1 * v0);   // L = 160+v
            if (!is0) {
                const float t3c = ncD * AL;
                G[161 + 2 * vv] = t3c * (v0 * sdot - p0 * (1.0f / 3.0f));
                G[192 + vv]     = t3c * (v1 * sdot - p1 * (1.0f / 3.0f));
                G[208 + vv]     = t3c * (v2 * sdot - p2 * (1.0f / 3.0f));
            } else {
                const float q = ncD * QZ;
                G[161 + 2 * vv] = q * p0;
                G[192 + vv]     = -2.0f * q * p1;
                G[208 + vv]     = q * p2;
            }
            #pragma unroll
            for (int m = 0; m < 2; m++) {
                const int lh = vv + 16 * m;
                hbuf[lh * 18 + bl] = fmaxf(fmaf(r, w1s[lh], b1s[lh]), 0.0f);
            }
        }

        if (c < 4) {
            const int b = bbase + (c + 1) * 16 + bl;
            gx = __ldg(geoA + b * 3 + 0);
            gy = __ldg(geoA + b * 3 + 1);
            gz = __ldg(geoA + b * 3 + 2);
            const float* f = fz + b * DIM;
            f0v = __ldg(f + vv);
            p0 = __ldg(f + 16 + 3 * vv);
            p1 = __ldg(f + 17 + 3 * vv);
            p2 = __ldg(f + 18 + 3 * vv);
        }
        __syncthreads();

        #pragma unroll 2
        for (int g16 = 0; g16 < 8; g16++) {
            float2 h2[4];
            #pragma unroll
            for (int m = 0; m < 4; m++)
                h2[m] = *(const float2*)(hbuf + (ty + 8 * m) * 18 + 2 * g16);
            #pragma unroll
            for (int jj = 0; jj < 2; jj++) {
                const float* grow = gbuf + (2 * g16 + jj) * 224;
                const ulonglong2 gg = *(const ulonglong2*)(grow + 4 * tx);
                const U64 g45 = *(const U64*)(grow + 128 + 2 * tx);
                const float gc = grow[192 + tx];
                #pragma unroll
                for (int m = 0; m < 4; m++) {
                    const float hs = jj ? h2[m].y : h2[m].x;
                    U64 hp; SPLAT2(hp, hs);
                    FMA2(S2[m][0], hp, gg.x);
                    FMA2(S2[m][1], hp, gg.y);
                    FMA2(S2[m][2], hp, g45);
                    S1[m] = fmaf(hs, gc, S1[m]);
                }
                FMA2(D2[0], hp8, gg.x);
                FMA2(D2[1], hp8, gg.y);
                FMA2(D2[2], hp8, g45);
                D1 = fmaf(h8, gc, D1);
            }
        }
    }

    float* base = g_S + (size_t)((blockIdx.z * 2 + z) * A + a) * SPIECE;
    #pragma unroll
    for (int m = 0; m < 4; m++) {
        float* rp = base + (ty + 8 * m) * SROW;
        const float2 s01 = *(const float2*)&S2[m][0];
        const float2 s23 = *(const float2*)&S2[m][1];
        *(float4*)(rp + 4 * tx) = make_float4(s01.x, s01.y, s23.x, s23.y);
        *(float2*)(rp + 128 + 2 * tx) = *(const float2*)&S2[m][2];
        rp[192 + tx] = S1[m];
    }
    if (p == 1 && ty == 0) {
        float* rp = base + 32 * SROW;
        const float2 d01 = *(const float2*)&D2[0];
        const float2 d23 = *(const float2*)&D2[1];
        *(float4*)(rp + 4 * tx) = make_float4(d01.x, d01.y, d23.x, d23.y);
        *(float2*)(rp + 128 + 2 * tx) = *(const float2*)&D2[2];
        rp[192 + tx] = D1;
    }
}

// ---- K2: both z per CTA, logical-order S, f32x2 contraction ----
__global__ void __launch_bounds__(256, 3)
out_kernel(const float* __restrict__ W2,
           const float* __restrict__ b2p)
{
    constexpr int A = 160, DIM = 64;
    extern __shared__ float S_sh[];     // [2][33][228] logical cols 0..223

    const int a = blockIdx.x, p = blockIdx.y;
    const int tid = threadIdx.x;

    // stage: un-permute + pb-sum, both z
    for (int i = tid; i < 2 * 33 * 56; i += 256) {
        const int zz = i / (33 * 56), rem = i % (33 * 56);
        const int row = rem / 56, c4 = rem % 56;
        const float* Q0 = g_S + (size_t)(((p * 2 + 0) * 2 + zz) * A + a) * SPIECE;
        const float* Q1 = g_S + (size_t)(((p * 2 + 1) * 2 + zz) * A + a) * SPIECE;
        const float4 x0 = *(const float4*)(Q0 + row * SROW + 4 * c4);
        const float4 x1 = *(const float4*)(Q1 + row * SROW + 4 * c4);
        const float4 s4 = make_float4(x0.x + x1.x, x0.y + x1.y,
                                      x0.z + x1.z, x0.w + x1.w);
        float* dst = S_sh + (zz * 33 + row) * SROW;
        if (c4 < 32) {                       // mem 4c..4c+3 -> L = c+32k
            dst[c4]      = s4.x;
            dst[32 + c4] = s4.y;
            dst[64 + c4] = s4.z;
            dst[96 + c4] = s4.w;
        } else if (c4 < 48) {                // mem 128+mm -> L = 128+32*(mm&1)+(mm>>1)
            const float sv[4] = {s4.x, s4.y, s4.z, s4.w};
            #pragma unroll
            for (int j = 0; j < 4; j++) {
                const int mm = 4 * (c4 - 32) + j;
                dst[128 + 32 * (mm & 1) + (mm >> 1)] = sv[j];
            }
        } else {                             // L = mem (192..223)
            *(float4*)(dst + 4 * c4) = s4;
        }
    }
    __syncthreads();

    const int oi = tid >> 2, part = tid & 3;
    U64 acc2[2] = {0, 0};
    const int hcnt = (part == 0 && p == 1) ? 9 : 8;
    if (oi < 16) {                                   // l=0 outputs (u = oi)
        const int u = oi;
        for (int t = 0; t < hcnt; t++) {
            const int lh = (t == 8) ? 32 : (4 * t + part);
            const ulonglong2* Wv = (const ulonglong2*)((lh == 32) ? b2p
                                       : (W2 + (size_t)(32 * p + lh) * 1536));
            #pragma unroll
            for (int v4 = 0; v4 < 4; v4++) {
                const ulonglong2 wa = Wv[u * 4 + v4];
                const ulonglong2 wb = Wv[64 + u * 4 + v4];
                #pragma unroll
                for (int zz = 0; zz < 2; zz++) {
                    const ulonglong2* Sv =
                        (const ulonglong2*)(S_sh + (zz * 33 + lh) * SROW);
                    const ulonglong2 s0 = Sv[v4];        // cols 4v4..
                    const ulonglong2 s1 = Sv[4 + v4];    // cols 16+4v4..
                    FMA2(acc2[zz], wa.x, s0.x);
                    FMA2(acc2[zz], wa.y, s0.y);
                    FMA2(acc2[zz], wb.x, s1.x);
                    FMA2(acc2[zz], wb.y, s1.y);
                }
            }
        }
    } else {                                         // l=1 outputs (u, i)
        const int qq = oi - 16;
        const int u  = qq / 3;
        const int i  = qq - 3 * u;
        const int CA = 8 + 4 * i;     // (32+16i)/4  in f4 units
        const int CB = 20 + 4 * i;    // (80+16i)/4
        const int CC = 32 + 4 * i;    // (128+16i)/4
        const int CD = 44 + 4 * i;    // (176+16i)/4
        for (int t = 0; t < hcnt; t++) {
            const int lh = (t == 8) ? 32 : (4 * t + part);
            const int row65 = (lh == 32) ? 64 : (32 * p + lh);
            const ulonglong2* Wv = (const ulonglong2*)((lh == 32) ? b2p
                                       : (W2 + (size_t)(32 * p + lh) * 1536));
            const ulonglong2* Wkv = (const ulonglong2*)(g_Wk + row65 * 768 + u * 48);
            #pragma unroll
            for (int v4 = 0; v4 < 4; v4++) {
                const ulonglong2 wc = Wv[128 + u * 4 + v4];
                const ulonglong2 k0 = Wkv[0 * 4 + v4];
                const ulonglong2 k1 = Wkv[1 * 4 + v4];
                const ulonglong2 k2 = Wkv[2 * 4 + v4];
                #pragma unroll
                for (int zz = 0; zz < 2; zz++) {
                    const ulonglong2* Sv =
                        (const ulonglong2*)(S_sh + (zz * 33 + lh) * SROW);
                    const ulonglong2 sA = Sv[CA + v4];
                    const ulonglong2 sB = Sv[CB + v4];
                    const ulonglong2 sC = Sv[CC + v4];
                    const ulonglong2 sD = Sv[CD + v4];
                    FMA2(acc2[zz], wc.x, sA.x);
                    FMA2(acc2[zz], wc.y, sA.y);
                    FMA2(acc2[zz], k0.x, sB.x);
                    FMA2(acc2[zz], k0.y, sB.y);
                    FMA2(acc2[zz], k1.x, sC.x);
                    FMA2(acc2[zz], k1.y, sC.y);
                    FMA2(acc2[zz], k2.x, sD.x);
                    FMA2(acc2[zz], k2.y, sD.y);
                }
            }
        }
    }
    float accz[2];
    #pragma unroll
    for (int zz = 0; zz < 2; zz++) {
        const float2 f = *(const float2*)&acc2[zz];
        float acc = f.x + f.y;
        acc += __shfl_down_sync(0xffffffffu, acc, 1);
        acc += __shfl_down_sync(0xffffffffu, acc, 2);
        accz[zz] = acc;
    }
    if (part == 0) {
        #pragma unroll
        for (int zz = 0; zz < 2; zz++)
            g_out[(size_t)(((p * 2 + zz) * A + a) * DIM) + oi] = accz[zz];
    }
}

__global__ void reduce_kernel(const float* __restrict__ maskp,
                              float* __restrict__ out)
{
    constexpr int NN = 2 * 160 * 64;
    const int i = blockIdx.x * 256 + threadIdx.x;
    if (i < NN) {
        const float s = g_out[i] + g_out[NN + i];
        out[i] = s * __ldg(maskp + (i >> 6));
    }
}

extern "C" void kernel_launch(void* const* d_in, const int* in_sizes, int n_in,
                              void* d_out, int out_size)
{
    const float* feat  = (const float*)d_in[0];
    const float* geo   = (const float*)d_in[1];
    const float* maskp = (const float*)d_in[2];
    const float* W1    = (const float*)d_in[3];
    const float* b1    = (const float*)d_in[4];
    const float* W2    = (const float*)d_in[5];
    const float* b2    = (const float*)d_in[6];
    float* out = (float*)d_out;

    const int smem1 = 8448 * 4;             // 33,792 B
    const int smem2 = 2 * 33 * SROW * 4;    // 60,192 B
    cudaFuncSetAttribute(conv_s_kernel, cudaFuncAttributeMaxDynamicSharedMemorySize,
                         smem1);
    cudaFuncSetAttribute(out_kernel, cudaFuncAttributeMaxDynamicSharedMemorySize,
                         smem2);
    prep_w_kernel<<<65, 256>>>(W2, b2);
    dim3 grid1(160, 2, 4);
    conv_s_kernel<<<grid1, 256, smem1>>>(feat, geo, W1, b1);
    dim3 grid2(160, 2);
    out_kernel<<<grid2, 256, smem2>>>(W2, b2);
    reduce_kernel<<<(2 * 160 * 64 + 255) / 256, 256>>>(maskp, out);
}